// round 9
// baseline (speedup 1.0000x reference)
#include <cuda_runtime.h>
#include <cuda_fp16.h>
#include <math.h>
#include <stdint.h>

// ---------------- problem constants ----------------
#define Nn 262144
#define Dd 64
#define Kk 64
#define TPB 256
#define OCC 3
#define GRID (148*OCC)            // 444 persistent CTAs
#define NCHUNK (Nn/16)            // 16384 m16 chunks
#define WSTRIDE (GRID*8)          // 3552 warps
#define LOG2PI_F 1.83787706640934548356f
#define EXP2_F 7.389056098930650f // exp(2) = exp(-prior_logvar_0)

// ---------------- device globals ----------------
__device__ double g_lse;
__device__ unsigned int g_count;

__device__ __forceinline__ void mma16(float c[4], const uint32_t a[4],
                                      uint32_t b0, uint32_t b1) {
    asm volatile("mma.sync.aligned.m16n8k16.row.col.f32.f16.f16.f32 "
        "{%0,%1,%2,%3},{%4,%5,%6,%7},{%8,%9},{%0,%1,%2,%3};"
        : "+f"(c[0]), "+f"(c[1]), "+f"(c[2]), "+f"(c[3])
        : "r"(a[0]), "r"(a[1]), "r"(a[2]), "r"(a[3]), "r"(b0), "r"(b1));
}
__device__ __forceinline__ uint32_t h2sq(uint32_t a) {
    __half2 h = *reinterpret_cast<__half2*>(&a);
    __half2 q = __hmul2(h, h);
    return *reinterpret_cast<uint32_t*>(&q);
}
__device__ __forceinline__ uint32_t f2h2(float lo, float hi) {
    __half2 h = __floats2half2_rn(lo, hi);
    return *reinterpret_cast<uint32_t*>(&h);
}

// ---------------------------------------------------------------------------
__global__ void __launch_bounds__(TPB, OCC)
gmm_kernel(const float* __restrict__ X,
           const float* __restrict__ u_noise,
           const float* __restrict__ phi_logits,
           const float* __restrict__ q_mu,
           const float* __restrict__ q_logvar,
           const float* __restrict__ pi_logits,
           const float* __restrict__ prior_p,
           float* __restrict__ out)
{
    // static smem (~20 KB): 9-tile B fragments + small vectors
    __shared__ float4 B_s[9 * 4 * 32];     // 18432 B
    __shared__ float  offs_s[64], lpi_s[64], phi_s[64];
    __shared__ float  scr[256];
    __shared__ float  kl_s, c0_s;
    __shared__ double wsum[TPB / 32];

    const int tid = threadIdx.x, wid = tid >> 5, lane = tid & 31;
    const int g = lane >> 2, t4 = lane & 3;

    // ---------------- in-CTA precompute ----------------
    if (tid < 64) {
        float uu  = u_noise[tid];
        float gmb = -__logf(-__logf(uu + 1e-9f) + 1e-9f);
        float pl  = phi_logits[tid];
        float phi = 1.0f / (1.0f + __expf(-(pl + gmb)));
        phi_s[tid] = phi;
        float qphi = 1.0f / (1.0f + __expf(-pl));
        qphi = fminf(fmaxf(qphi, 1e-6f), 1.0f - 1e-6f);
        if (blockIdx.x == 0) out[1 + tid] = qphi;
        float p = fminf(fmaxf(prior_p[tid], 1e-6f), 1.0f - 1e-6f);
        scr[tid]       = qphi * (__logf(qphi) - __logf(p))
                       + (1.0f - qphi) * (__logf(1.0f - qphi) - __logf(1.0f - p));
        scr[64 + tid]  = (1.0f - phi) * (LOG2PI_F - 2.0f);
        scr[128 + tid] = pi_logits[tid];
    }
    __syncthreads();
    if (tid == 0) {
        float kl = 0.f, c0 = 0.f;
        #pragma unroll
        for (int i = 0; i < 64; i++) { kl += scr[i]; c0 += scr[64 + i]; }
        kl_s = kl; c0_s = c0;
    }
    if (tid < 64) {     // log(softmax(pi)+1e-9)
        float m = -3.4e38f;
        #pragma unroll
        for (int k = 0; k < 64; k++) m = fmaxf(m, scr[128 + k]);
        float ss = 0.f;
        #pragma unroll
        for (int k = 0; k < 64; k++) ss += __expf(scr[128 + k] - m);
        lpi_s[tid] = __logf(__expf(scr[128 + tid] - m) / ss + 1e-9f);
    }

    // packed B fragments (9 n-tiles: clusters 0..63, col 64 = background):
    // entry e = (j*4 + ks)*32 + le
    // float4 = { h2(lin d0,d0+1), h2(lin d0+8,d0+9), h2(qd d0,d0+1), h2(qd d0+8,d0+9) }
    for (int e = tid; e < 9 * 4 * 32; e += TPB) {
        int le = e & 31, ks = (e >> 5) & 3, j = e >> 7;
        int n = 8 * j + (le >> 2);
        int d0 = 16 * ks + 2 * (le & 3);
        float lin[4] = {0.f, 0.f, 0.f, 0.f}, qd[4] = {0.f, 0.f, 0.f, 0.f};
        if (n < Kk) {
            #pragma unroll
            for (int p = 0; p < 4; p++) {
                int d = d0 + (p & 1) + (p >> 1) * 8;   // d0, d0+1, d0+8, d0+9
                float lv = fminf(fmaxf(q_logvar[n * Dd + d], -5.0f), 5.0f);
                float a  = phi_s[d] * __expf(-lv);
                qd[p]  = a;
                lin[p] = -2.0f * q_mu[n * Dd + d] * a;
            }
        } else if (n == Kk) {
            #pragma unroll
            for (int p = 0; p < 4; p++) {
                int d = d0 + (p & 1) + (p >> 1) * 8;
                qd[p] = (1.0f - phi_s[d]) * EXP2_F;    // background weights
            }
        }
        float4 v;
        *(uint32_t*)&v.x = f2h2(lin[0], lin[1]);
        *(uint32_t*)&v.y = f2h2(lin[2], lin[3]);
        *(uint32_t*)&v.z = f2h2(qd[0],  qd[1]);
        *(uint32_t*)&v.w = f2h2(qd[2],  qd[3]);
        B_s[e] = v;
    }
    __syncthreads();    // scr free; reuse for offs partials
    {
        int k = tid & 63, part = tid >> 6;
        float s = 0.f;
        #pragma unroll
        for (int d = part * 16; d < part * 16 + 16; d++) {
            float lv = fminf(fmaxf(q_logvar[k * Dd + d], -5.0f), 5.0f);
            float a  = phi_s[d] * __expf(-lv);
            float mu = q_mu[k * Dd + d];
            s += phi_s[d] * (LOG2PI_F + lv) + mu * mu * a;
        }
        scr[tid] = s;
    }
    __syncthreads();
    if (tid < 64)
        offs_s[tid] = -0.5f * (scr[tid] + scr[64 + tid] + scr[128 + tid] + scr[192 + tid]);
    __syncthreads();    // LAST block sync; smem read-only below

    const float C0 = c0_s;
    const int gwarp = blockIdx.x * 8 + wid;
    double lsesum = 0.0;

    // =================== independent per-warp chunk loop ===================
    for (int chunk = gwarp; chunk < NCHUNK; chunk += WSTRIDE) {
        const int row0 = chunk * 16;
        const float2* Xg = (const float2*)X + (size_t)(row0 + g) * 32 + t4;

        // ---- batched loads -> immediate fp16 conversion (v dies fast) ----
        uint32_t A[4][4], Q[4][4];
        #pragma unroll
        for (int ks = 0; ks < 4; ks++) {
            float2 v0 = Xg[8 * ks];              // row g,   cols 16ks+2t4
            float2 v1 = Xg[8 * 32 + 8 * ks];     // row g+8
            float2 v2 = Xg[8 * ks + 4];          // row g,   +8
            float2 v3 = Xg[8 * 32 + 8 * ks + 4]; // row g+8, +8
            A[ks][0] = f2h2(v0.x, v0.y);  Q[ks][0] = h2sq(A[ks][0]);
            A[ks][1] = f2h2(v1.x, v1.y);  Q[ks][1] = h2sq(A[ks][1]);
            A[ks][2] = f2h2(v2.x, v2.y);  Q[ks][2] = h2sq(A[ks][2]);
            A[ks][3] = f2h2(v3.x, v3.y);  Q[ks][3] = h2sq(A[ks][3]);
        }

        // ---- MMA: 4 ksteps x 9 n-tiles x (lin + quad) ----
        float c[9][4];
        #pragma unroll
        for (int j = 0; j < 9; j++)
            { c[j][0]=0.f; c[j][1]=0.f; c[j][2]=0.f; c[j][3]=0.f; }
        #pragma unroll
        for (int ks = 0; ks < 4; ks++) {
            const float4* bp = B_s + ks * 32 + lane;
            #pragma unroll
            for (int j = 0; j < 9; j++) {
                float4 b = bp[j * 128];
                mma16(c[j], A[ks], *(uint32_t*)&b.x, *(uint32_t*)&b.y);
                mma16(c[j], Q[ks], *(uint32_t*)&b.z, *(uint32_t*)&b.w);
            }
        }

        // ---- epilogue: rows g (h=0) and g+8 (h=1) ----
        #pragma unroll
        for (int h = 0; h < 2; h++) {
            float bgq  = __shfl_sync(0xffffffffu, c[8][2 * h], lane & ~3);
            float lpbg = -0.5f * (C0 + bgq);
            float lp[16];
            float mx = -3.4e38f;
            #pragma unroll
            for (int j = 0; j < 8; j++) {
                int col = 8 * j + 2 * t4;
                float v0 = fmaf(-0.5f, c[j][2*h],   offs_s[col])   + lpbg;
                float v1 = fmaf(-0.5f, c[j][2*h+1], offs_s[col+1]) + lpbg;
                lp[2*j] = v0; lp[2*j+1] = v1;
                mx = fmaxf(mx, fmaxf(v0 + lpi_s[col], v1 + lpi_s[col+1]));
            }
            mx = fmaxf(mx, __shfl_xor_sync(0xffffffffu, mx, 1));
            mx = fmaxf(mx, __shfl_xor_sync(0xffffffffu, mx, 2));
            float se = 0.f;
            #pragma unroll
            for (int j = 0; j < 8; j++) {
                int col = 8 * j + 2 * t4;
                se += __expf(lp[2*j]   + lpi_s[col]   - mx);
                se += __expf(lp[2*j+1] + lpi_s[col+1] - mx);
            }
            se += __shfl_xor_sync(0xffffffffu, se, 1);
            se += __shfl_xor_sync(0xffffffffu, se, 2);
            if (t4 == 0) lsesum += (double)(mx + __logf(se));

            float* op = out + 65 + (size_t)(row0 + g + 8 * h) * Kk;
            #pragma unroll
            for (int j = 0; j < 8; j++) {
                op[8*j + 2*t4]     = lp[2*j];
                op[8*j + 2*t4 + 1] = lp[2*j+1];
            }
        }
    }

    // ---- loss reduce + last-CTA finalize (deterministic replay reset) ----
    #pragma unroll
    for (int s = 16; s; s >>= 1)
        lsesum += __shfl_xor_sync(0xffffffffu, lsesum, s);
    if (lane == 0) wsum[wid] = lsesum;
    __syncthreads();
    if (tid == 0) {
        double bsum = 0.0;
        #pragma unroll
        for (int w = 0; w < TPB / 32; w++) bsum += wsum[w];
        atomicAdd(&g_lse, bsum);
        __threadfence();
        unsigned int old = atomicAdd(&g_count, 1u);
        if (old == GRID - 1) {
            __threadfence();
            double total = atomicAdd(&g_lse, 0.0);
            out[0] = (float)((double)kl_s * (double)Nn - total);
            g_lse   = 0.0;
            g_count = 0u;
        }
    }
}

// ---------------------------------------------------------------------------
extern "C" void kernel_launch(void* const* d_in, const int* in_sizes, int n_in,
                              void* d_out, int out_size)
{
    const float* X  = (const float*)d_in[0];
    const float* u  = (const float*)d_in[1];
    const float* pl = (const float*)d_in[2];
    const float* mu = (const float*)d_in[3];
    const float* lv = (const float*)d_in[4];
    const float* pi = (const float*)d_in[5];
    const float* pp = (const float*)d_in[6];
    float* out = (float*)d_out;

    gmm_kernel<<<GRID, TPB>>>(X, u, pl, mu, lv, pi, pp, out);
}

// round 11
// speedup vs baseline: 1.0857x; 1.0857x over previous
#include <cuda_runtime.h>
#include <cuda_fp16.h>
#include <math.h>
#include <stdint.h>

// ---------------- problem constants ----------------
#define Nn 262144
#define Dd 64
#define Kk 64
#define TPB 256
#define GRID 296                 // persistent CTAs (2/SM x 148)
#define NCHUNK (Nn/16)           // 16384 m16 chunks
#define WSTRIDE (GRID*8)         // 2368 warps
#define LOG2PI_F 1.83787706640934548356f
#define EXP2_F 7.389056098930650f    // exp(2) = exp(-prior_logvar_0)
#define LOG2E_F 1.44269504088896340736f

// ---------------- device globals ----------------
__device__ double g_lse;
__device__ unsigned int g_count;

__device__ __forceinline__ void mma16(float c[4], const uint32_t a[4],
                                      uint32_t b0, uint32_t b1) {
    asm volatile("mma.sync.aligned.m16n8k16.row.col.f32.f16.f16.f32 "
        "{%0,%1,%2,%3},{%4,%5,%6,%7},{%8,%9},{%0,%1,%2,%3};"
        : "+f"(c[0]), "+f"(c[1]), "+f"(c[2]), "+f"(c[3])
        : "r"(a[0]), "r"(a[1]), "r"(a[2]), "r"(a[3]), "r"(b0), "r"(b1));
}
__device__ __forceinline__ uint32_t h2sq(uint32_t a) {
    __half2 h = *reinterpret_cast<__half2*>(&a);
    __half2 q = __hmul2(h, h);
    return *reinterpret_cast<uint32_t*>(&q);
}
__device__ __forceinline__ uint32_t f2h2(float lo, float hi) {
    __half2 h = __floats2half2_rn(lo, hi);
    return *reinterpret_cast<uint32_t*>(&h);
}
// two exps per MUFU op
__device__ __forceinline__ __half2 ex2_h2(float z0, float z1) {
    __half2 z = __floats2half2_rn(z0, z1);
    uint32_t zi = *reinterpret_cast<uint32_t*>(&z), r;
    asm("ex2.approx.f16x2 %0, %1;" : "=r"(r) : "r"(zi));
    return *reinterpret_cast<__half2*>(&r);
}

// ---------------------------------------------------------------------------
__global__ void __launch_bounds__(TPB, 2)
gmm_kernel(const float* __restrict__ X,
           const float* __restrict__ u_noise,
           const float* __restrict__ phi_logits,
           const float* __restrict__ q_mu,
           const float* __restrict__ q_logvar,
           const float* __restrict__ pi_logits,
           const float* __restrict__ prior_p,
           float* __restrict__ out)
{
    __shared__ float4 B_s[8 * 4 * 32];     // packed B frags (16 KB)
    __shared__ float  offs_s[64], lpi_s[64], wbg_s[64], phi_s[64];
    __shared__ float  scr[256];
    __shared__ float  kl_s, c0_s;
    __shared__ double wsum[TPB / 32];

    const int tid = threadIdx.x, wid = tid >> 5, lane = tid & 31;
    const int g = lane >> 2, t4 = lane & 3;

    // ---------------- in-CTA precompute ----------------
    if (tid < 64) {
        float uu  = u_noise[tid];
        float gmb = -__logf(-__logf(uu + 1e-9f) + 1e-9f);
        float pl  = phi_logits[tid];
        float phi = 1.0f / (1.0f + __expf(-(pl + gmb)));
        phi_s[tid] = phi;
        float qphi = 1.0f / (1.0f + __expf(-pl));
        qphi = fminf(fmaxf(qphi, 1e-6f), 1.0f - 1e-6f);
        if (blockIdx.x == 0) out[1 + tid] = qphi;
        float p = fminf(fmaxf(prior_p[tid], 1e-6f), 1.0f - 1e-6f);
        scr[tid]       = qphi * (__logf(qphi) - __logf(p))
                       + (1.0f - qphi) * (__logf(1.0f - qphi) - __logf(1.0f - p));
        scr[64 + tid]  = (1.0f - phi) * (LOG2PI_F - 2.0f);
        scr[128 + tid] = pi_logits[tid];
        wbg_s[tid]     = (1.0f - phi) * EXP2_F;
    }
    __syncthreads();
    if (tid == 0) {
        float kl = 0.f, c0 = 0.f;
        #pragma unroll
        for (int i = 0; i < 64; i++) { kl += scr[i]; c0 += scr[64 + i]; }
        kl_s = kl; c0_s = c0;
    }
    if (tid < 64) {     // log(softmax(pi)+1e-9)
        float m = -3.4e38f;
        #pragma unroll
        for (int k = 0; k < 64; k++) m = fmaxf(m, scr[128 + k]);
        float ss = 0.f;
        #pragma unroll
        for (int k = 0; k < 64; k++) ss += __expf(scr[128 + k] - m);
        lpi_s[tid] = __logf(__expf(scr[128 + tid] - m) / ss + 1e-9f);
    }

    // packed B fragments: entry e = (j*4 + ks)*32 + le
    for (int e = tid; e < 8 * 4 * 32; e += TPB) {
        int le = e & 31, ks = (e >> 5) & 3, j = e >> 7;
        int n = 8 * j + (le >> 2);
        int d0 = 16 * ks + 2 * (le & 3);
        float lin[4], aa[4];
        #pragma unroll
        for (int p = 0; p < 4; p++) {
            int d = d0 + (p & 1) + (p >> 1) * 8;        // d0, d0+1, d0+8, d0+9
            float lv = fminf(fmaxf(q_logvar[n * Dd + d], -5.0f), 5.0f);
            float a  = phi_s[d] * __expf(-lv);
            aa[p]  = a;
            lin[p] = -2.0f * q_mu[n * Dd + d] * a;
        }
        float4 v;
        *(uint32_t*)&v.x = f2h2(lin[0], lin[1]);
        *(uint32_t*)&v.y = f2h2(lin[2], lin[3]);
        *(uint32_t*)&v.z = f2h2(aa[0],  aa[1]);
        *(uint32_t*)&v.w = f2h2(aa[2],  aa[3]);
        B_s[e] = v;
    }
    __syncthreads();    // scr free; reuse for offs partials
    {
        int k = tid & 63, part = tid >> 6;
        float s = 0.f;
        #pragma unroll
        for (int d = part * 16; d < part * 16 + 16; d++) {
            float lv = fminf(fmaxf(q_logvar[k * Dd + d], -5.0f), 5.0f);
            float a  = phi_s[d] * __expf(-lv);
            float mu = q_mu[k * Dd + d];
            s += phi_s[d] * (LOG2PI_F + lv) + mu * mu * a;
        }
        scr[tid] = s;
    }
    __syncthreads();
    if (tid < 64)
        offs_s[tid] = -0.5f * (scr[tid] + scr[64 + tid] + scr[128 + tid] + scr[192 + tid]);
    __syncthreads();    // LAST sync: smem read-only from here

    const float C0 = c0_s;
    const int gwarp = blockIdx.x * 8 + wid;
    double lsesum = 0.0;

    // hoisted background weights for this lane's columns
    float2 wq[4][2];
    #pragma unroll
    for (int ks = 0; ks < 4; ks++) {
        wq[ks][0] = *(const float2*)(wbg_s + 16 * ks + 2 * t4);
        wq[ks][1] = *(const float2*)(wbg_s + 16 * ks + 2 * t4 + 8);
    }

    // =================== independent per-warp chunk loop ===================
    for (int chunk = gwarp; chunk < NCHUNK; chunk += WSTRIDE) {
        const int row0 = chunk * 16;
        const float2* Xg = (const float2*)X + (size_t)(row0 + g) * 32 + t4;

        // ---- batched fragment loads (16 LDG.64, full MLP) ----
        float2 v[4][4];
        #pragma unroll
        for (int ks = 0; ks < 4; ks++) {
            v[ks][0] = Xg[8 * ks];             // row g,   cols 16ks+2t4..+1
            v[ks][1] = Xg[8 * 32 + 8 * ks];    // row g+8
            v[ks][2] = Xg[8 * ks + 4];         // row g,   cols +8
            v[ks][3] = Xg[8 * 32 + 8 * ks + 4];
        }

        // ---- fp16 frags, squares, exact fp32 bg partials ----
        uint32_t A[4][4], Q[4][4];
        float bg0 = 0.f, bg1 = 0.f;
        #pragma unroll
        for (int ks = 0; ks < 4; ks++) {
            #pragma unroll
            for (int p = 0; p < 4; p++) {
                A[ks][p] = f2h2(v[ks][p].x, v[ks][p].y);
                Q[ks][p] = h2sq(A[ks][p]);
            }
            bg0 = fmaf(wq[ks][0].x, v[ks][0].x * v[ks][0].x, bg0);
            bg0 = fmaf(wq[ks][0].y, v[ks][0].y * v[ks][0].y, bg0);
            bg0 = fmaf(wq[ks][1].x, v[ks][2].x * v[ks][2].x, bg0);
            bg0 = fmaf(wq[ks][1].y, v[ks][2].y * v[ks][2].y, bg0);
            bg1 = fmaf(wq[ks][0].x, v[ks][1].x * v[ks][1].x, bg1);
            bg1 = fmaf(wq[ks][0].y, v[ks][1].y * v[ks][1].y, bg1);
            bg1 = fmaf(wq[ks][1].x, v[ks][3].x * v[ks][3].x, bg1);
            bg1 = fmaf(wq[ks][1].y, v[ks][3].y * v[ks][3].y, bg1);
        }
        bg0 += __shfl_xor_sync(0xffffffffu, bg0, 1);
        bg0 += __shfl_xor_sync(0xffffffffu, bg0, 2);
        bg1 += __shfl_xor_sync(0xffffffffu, bg1, 1);
        bg1 += __shfl_xor_sync(0xffffffffu, bg1, 2);

        // ---- MMA: 4 ksteps x 8 n-tiles x (lin + quad) ----
        float c[8][4];
        #pragma unroll
        for (int j = 0; j < 8; j++)
            { c[j][0]=0.f; c[j][1]=0.f; c[j][2]=0.f; c[j][3]=0.f; }
        #pragma unroll
        for (int ks = 0; ks < 4; ks++) {
            const float4* bp = B_s + ks * 32 + lane;
            #pragma unroll
            for (int j = 0; j < 8; j++) {
                float4 b = bp[j * 128];
                mma16(c[j], A[ks], *(uint32_t*)&b.x, *(uint32_t*)&b.y);
                mma16(c[j], Q[ks], *(uint32_t*)&b.z, *(uint32_t*)&b.w);
            }
        }

        // ---- epilogue: rows g (h=0) and g+8 (h=1) ----
        #pragma unroll
        for (int h = 0; h < 2; h++) {
            float lpbg = -0.5f * (C0 + (h ? bg1 : bg0));
            float lp[16], y[16];
            float mx = -3.4e38f;
            #pragma unroll
            for (int j = 0; j < 8; j++) {
                int col = 8 * j + 2 * t4;
                float v0 = fmaf(-0.5f, c[j][2*h],   offs_s[col])   + lpbg;
                float v1 = fmaf(-0.5f, c[j][2*h+1], offs_s[col+1]) + lpbg;
                lp[2*j] = v0; lp[2*j+1] = v1;
                y[2*j]   = v0 + lpi_s[col];
                y[2*j+1] = v1 + lpi_s[col+1];
                mx = fmaxf(mx, fmaxf(y[2*j], y[2*j+1]));
            }
            mx = fmaxf(mx, __shfl_xor_sync(0xffffffffu, mx, 1));
            mx = fmaxf(mx, __shfl_xor_sync(0xffffffffu, mx, 2));

            // exp via ex2.approx.f16x2 (1 MUFU per 2 terms), tree-summed
            float mxl = mx * LOG2E_F;
            __half2 e0 = ex2_h2(fmaf(y[0],  LOG2E_F, -mxl), fmaf(y[1],  LOG2E_F, -mxl));
            __half2 e1 = ex2_h2(fmaf(y[2],  LOG2E_F, -mxl), fmaf(y[3],  LOG2E_F, -mxl));
            __half2 e2 = ex2_h2(fmaf(y[4],  LOG2E_F, -mxl), fmaf(y[5],  LOG2E_F, -mxl));
            __half2 e3 = ex2_h2(fmaf(y[6],  LOG2E_F, -mxl), fmaf(y[7],  LOG2E_F, -mxl));
            __half2 e4 = ex2_h2(fmaf(y[8],  LOG2E_F, -mxl), fmaf(y[9],  LOG2E_F, -mxl));
            __half2 e5 = ex2_h2(fmaf(y[10], LOG2E_F, -mxl), fmaf(y[11], LOG2E_F, -mxl));
            __half2 e6 = ex2_h2(fmaf(y[12], LOG2E_F, -mxl), fmaf(y[13], LOG2E_F, -mxl));
            __half2 e7 = ex2_h2(fmaf(y[14], LOG2E_F, -mxl), fmaf(y[15], LOG2E_F, -mxl));
            __half2 s01 = __hadd2(e0, e1), s23 = __hadd2(e2, e3);
            __half2 s45 = __hadd2(e4, e5), s67 = __hadd2(e6, e7);
            float2 f0 = __half22float2(s01), f1 = __half22float2(s23);
            float2 f2 = __half22float2(s45), f3 = __half22float2(s67);
            float se = (f0.x + f0.y) + (f1.x + f1.y)
                     + (f2.x + f2.y) + (f3.x + f3.y);
            se += __shfl_xor_sync(0xffffffffu, se, 1);
            se += __shfl_xor_sync(0xffffffffu, se, 2);
            if (t4 == 0) lsesum += (double)(mx + __logf(se));

            // scalar STG.32: out+65 is only 4B-aligned — float2 stores trap
            float* op = out + 65 + (size_t)(row0 + g + 8 * h) * Kk;
            #pragma unroll
            for (int j = 0; j < 8; j++) {
                op[8*j + 2*t4]     = lp[2*j];
                op[8*j + 2*t4 + 1] = lp[2*j+1];
            }
        }
    }

    // ---- loss reduce + last-CTA finalize (deterministic replay reset) ----
    #pragma unroll
    for (int s = 16; s; s >>= 1)
        lsesum += __shfl_xor_sync(0xffffffffu, lsesum, s);
    if (lane == 0) wsum[wid] = lsesum;
    __syncthreads();
    if (tid == 0) {
        double bsum = 0.0;
        #pragma unroll
        for (int w = 0; w < TPB / 32; w++) bsum += wsum[w];
        atomicAdd(&g_lse, bsum);
        __threadfence();
        unsigned int old = atomicAdd(&g_count, 1u);
        if (old == GRID - 1) {
            __threadfence();
            double total = atomicAdd(&g_lse, 0.0);
            out[0] = (float)((double)kl_s * (double)Nn - total);
            g_lse   = 0.0;
            g_count = 0u;
        }
    }
}

// ---------------------------------------------------------------------------
extern "C" void kernel_launch(void* const* d_in, const int* in_sizes, int n_in,
                              void* d_out, int out_size)
{
    const float* X  = (const float*)d_in[0];
    const float* u  = (const float*)d_in[1];
    const float* pl = (const float*)d_in[2];
    const float* mu = (const float*)d_in[3];
    const float* lv = (const float*)d_in[4];
    const float* pi = (const float*)d_in[5];
    const float* pp = (const float*)d_in[6];
    float* out = (float*)d_out;

    gmm_kernel<<<GRID, TPB>>>(X, u, pl, mu, lv, pi, pp, out);
}

// round 12
// speedup vs baseline: 1.2359x; 1.1383x over previous
#include <cuda_runtime.h>
#include <cuda_fp16.h>
#include <math.h>
#include <stdint.h>

// ---------------- problem constants ----------------
#define Nn 262144
#define Dd 64
#define Kk 64
#define TPB 256
#define GRID 296                 // persistent CTAs (2/SM x 148)
#define NCH (Nn/32)              // 8192 m32 chunks
#define LOG2PI_F 1.83787706640934548356f
#define EXP2_F 7.389056098930650f     // exp(2) = exp(-prior_logvar_0)
#define LOG2E_F 1.44269504088896340736f

// ---------------- smem layout (bytes, dynamic) ----------------
#define OFF_B     0               // 8*4*32 float4 = 16384
#define OFF_STG   16384           // 8 warps * 16*68 floats = 34816
#define OFF_OFFS  51200           // 64 f32
#define OFF_LPI   51456
#define OFF_WBG   51712
#define OFF_PHI   51968
#define OFF_SCR   52224           // 256 f32
#define SMEM_BYTES 53248

// ---------------- device globals ----------------
__device__ double g_lse;
__device__ unsigned int g_count;
__device__ unsigned int g_tile;

__device__ __forceinline__ void mma16(float c[4], const uint32_t a[4],
                                      uint32_t b0, uint32_t b1) {
    asm volatile("mma.sync.aligned.m16n8k16.row.col.f32.f16.f16.f32 "
        "{%0,%1,%2,%3},{%4,%5,%6,%7},{%8,%9},{%0,%1,%2,%3};"
        : "+f"(c[0]), "+f"(c[1]), "+f"(c[2]), "+f"(c[3])
        : "r"(a[0]), "r"(a[1]), "r"(a[2]), "r"(a[3]), "r"(b0), "r"(b1));
}
__device__ __forceinline__ uint32_t h2sq(uint32_t a) {
    __half2 h = *reinterpret_cast<__half2*>(&a);
    __half2 q = __hmul2(h, h);
    return *reinterpret_cast<uint32_t*>(&q);
}
__device__ __forceinline__ uint32_t f2h2(float lo, float hi) {
    __half2 h = __floats2half2_rn(lo, hi);
    return *reinterpret_cast<uint32_t*>(&h);
}
__device__ __forceinline__ __half2 ex2_h2(float z0, float z1) {
    __half2 z = __floats2half2_rn(z0, z1);
    uint32_t zi = *reinterpret_cast<uint32_t*>(&z), r;
    asm("ex2.approx.f16x2 %0, %1;" : "=r"(r) : "r"(zi));
    return *reinterpret_cast<__half2*>(&r);
}

// ---------------------------------------------------------------------------
__global__ void __launch_bounds__(TPB, 2)
gmm_kernel(const float* __restrict__ X,
           const float* __restrict__ u_noise,
           const float* __restrict__ phi_logits,
           const float* __restrict__ q_mu,
           const float* __restrict__ q_logvar,
           const float* __restrict__ pi_logits,
           const float* __restrict__ prior_p,
           float* __restrict__ out)
{
    extern __shared__ char smraw[];
    float4* B_s    = (float4*)(smraw + OFF_B);
    float*  offs_s = (float*) (smraw + OFF_OFFS);
    float*  lpi_s  = (float*) (smraw + OFF_LPI);
    float*  wbg_s  = (float*) (smraw + OFF_WBG);
    float*  phi_s  = (float*) (smraw + OFF_PHI);
    float*  scr    = (float*) (smraw + OFF_SCR);

    __shared__ float kl_s, c0_s;
    __shared__ double wsum[TPB / 32];

    const int tid = threadIdx.x, wid = tid >> 5, lane = tid & 31;
    const int g = lane >> 2, t4 = lane & 3;
    float* stg = (float*)(smraw + OFF_STG) + wid * (16 * 68);   // warp-private

    // ---------------- in-CTA precompute ----------------
    if (tid < 64) {
        float uu  = u_noise[tid];
        float gmb = -__logf(-__logf(uu + 1e-9f) + 1e-9f);
        float pl  = phi_logits[tid];
        float phi = 1.0f / (1.0f + __expf(-(pl + gmb)));
        phi_s[tid] = phi;
        float qphi = 1.0f / (1.0f + __expf(-pl));
        qphi = fminf(fmaxf(qphi, 1e-6f), 1.0f - 1e-6f);
        if (blockIdx.x == 0) out[1 + tid] = qphi;
        float p = fminf(fmaxf(prior_p[tid], 1e-6f), 1.0f - 1e-6f);
        scr[tid]       = qphi * (__logf(qphi) - __logf(p))
                       + (1.0f - qphi) * (__logf(1.0f - qphi) - __logf(1.0f - p));
        scr[64 + tid]  = (1.0f - phi) * (LOG2PI_F - 2.0f);
        scr[128 + tid] = pi_logits[tid];
        wbg_s[tid]     = (1.0f - phi) * EXP2_F;
    }
    __syncthreads();
    if (tid == 0) {
        float kl = 0.f, c0 = 0.f;
        #pragma unroll
        for (int i = 0; i < 64; i++) { kl += scr[i]; c0 += scr[64 + i]; }
        kl_s = kl; c0_s = c0;
    }
    if (tid < 64) {     // log(softmax(pi)+1e-9)
        float m = -3.4e38f;
        #pragma unroll
        for (int k = 0; k < 64; k++) m = fmaxf(m, scr[128 + k]);
        float ss = 0.f;
        #pragma unroll
        for (int k = 0; k < 64; k++) ss += __expf(scr[128 + k] - m);
        lpi_s[tid] = __logf(__expf(scr[128 + tid] - m) / ss + 1e-9f);
    }

    // packed B fragments: entry e = (j*4 + ks)*32 + le
    for (int e = tid; e < 8 * 4 * 32; e += TPB) {
        int le = e & 31, ks = (e >> 5) & 3, j = e >> 7;
        int n = 8 * j + (le >> 2);
        int d0 = 16 * ks + 2 * (le & 3);
        float lin[4], aa[4];
        #pragma unroll
        for (int p = 0; p < 4; p++) {
            int d = d0 + (p & 1) + (p >> 1) * 8;        // d0, d0+1, d0+8, d0+9
            float lv = fminf(fmaxf(q_logvar[n * Dd + d], -5.0f), 5.0f);
            float a  = phi_s[d] * __expf(-lv);
            aa[p]  = a;
            lin[p] = -2.0f * q_mu[n * Dd + d] * a;
        }
        float4 v;
        *(uint32_t*)&v.x = f2h2(lin[0], lin[1]);
        *(uint32_t*)&v.y = f2h2(lin[2], lin[3]);
        *(uint32_t*)&v.z = f2h2(aa[0],  aa[1]);
        *(uint32_t*)&v.w = f2h2(aa[2],  aa[3]);
        B_s[e] = v;
    }
    __syncthreads();    // scr free; reuse for offs partials
    {
        int k = tid & 63, part = tid >> 6;
        float s = 0.f;
        #pragma unroll
        for (int d = part * 16; d < part * 16 + 16; d++) {
            float lv = fminf(fmaxf(q_logvar[k * Dd + d], -5.0f), 5.0f);
            float a  = phi_s[d] * __expf(-lv);
            float mu = q_mu[k * Dd + d];
            s += phi_s[d] * (LOG2PI_F + lv) + mu * mu * a;
        }
        scr[tid] = s;
    }
    __syncthreads();
    if (tid < 64)
        offs_s[tid] = -0.5f * (scr[tid] + scr[64 + tid] + scr[128 + tid] + scr[192 + tid]);
    __syncthreads();    // LAST block sync; shared tables read-only below

    const float C0 = c0_s;
    double lsesum = 0.0;

    // =================== work-stealing per-warp m32 chunk loop ===================
    for (;;) {
        unsigned int tile;
        if (lane == 0) tile = atomicAdd(&g_tile, 1u);
        tile = __shfl_sync(0xffffffffu, tile, 0);
        if (tile >= NCH) break;
        const int row0 = (int)tile * 32;
        const float2* Xg = (const float2*)X + (size_t)(row0 + g) * 32 + t4;

        float c[2][8][4];
        #pragma unroll
        for (int u = 0; u < 2; u++)
            #pragma unroll
            for (int j = 0; j < 8; j++)
                { c[u][j][0]=0.f; c[u][j][1]=0.f; c[u][j][2]=0.f; c[u][j][3]=0.f; }
        float bg[4] = {0.f, 0.f, 0.f, 0.f};   // rows g, g+8, g+16, g+24

        #pragma unroll
        for (int ks = 0; ks < 4; ks++) {
            // tile0: rows g, g+8 ; tile1: rows g+16, g+24 (row stride = 32 float2)
            float2 v00 = Xg[8 * ks],         v01 = Xg[256 + 8 * ks];
            float2 v02 = Xg[8 * ks + 4],     v03 = Xg[256 + 8 * ks + 4];
            float2 v10 = Xg[512 + 8 * ks],   v11 = Xg[768 + 8 * ks];
            float2 v12 = Xg[512 + 8 * ks + 4], v13 = Xg[768 + 8 * ks + 4];

            float2 w0 = *(const float2*)(wbg_s + 16 * ks + 2 * t4);
            float2 w1 = *(const float2*)(wbg_s + 16 * ks + 2 * t4 + 8);
            bg[0] = fmaf(w0.x, v00.x*v00.x, fmaf(w0.y, v00.y*v00.y,
                     fmaf(w1.x, v02.x*v02.x, fmaf(w1.y, v02.y*v02.y, bg[0]))));
            bg[1] = fmaf(w0.x, v01.x*v01.x, fmaf(w0.y, v01.y*v01.y,
                     fmaf(w1.x, v03.x*v03.x, fmaf(w1.y, v03.y*v03.y, bg[1]))));
            bg[2] = fmaf(w0.x, v10.x*v10.x, fmaf(w0.y, v10.y*v10.y,
                     fmaf(w1.x, v12.x*v12.x, fmaf(w1.y, v12.y*v12.y, bg[2]))));
            bg[3] = fmaf(w0.x, v11.x*v11.x, fmaf(w0.y, v11.y*v11.y,
                     fmaf(w1.x, v13.x*v13.x, fmaf(w1.y, v13.y*v13.y, bg[3]))));

            uint32_t A0[4] = { f2h2(v00.x,v00.y), f2h2(v01.x,v01.y),
                               f2h2(v02.x,v02.y), f2h2(v03.x,v03.y) };
            uint32_t A1[4] = { f2h2(v10.x,v10.y), f2h2(v11.x,v11.y),
                               f2h2(v12.x,v12.y), f2h2(v13.x,v13.y) };
            uint32_t Q0[4] = { h2sq(A0[0]), h2sq(A0[1]), h2sq(A0[2]), h2sq(A0[3]) };
            uint32_t Q1[4] = { h2sq(A1[0]), h2sq(A1[1]), h2sq(A1[2]), h2sq(A1[3]) };

            const float4* bp = B_s + ks * 32 + lane;
            #pragma unroll
            for (int j = 0; j < 8; j++) {
                float4 b = bp[j * 128];               // one LDS.128, reused 4x
                uint32_t bl0 = *(uint32_t*)&b.x, bl1 = *(uint32_t*)&b.y;
                uint32_t bq0 = *(uint32_t*)&b.z, bq1 = *(uint32_t*)&b.w;
                mma16(c[0][j], A0, bl0, bl1);
                mma16(c[0][j], Q0, bq0, bq1);
                mma16(c[1][j], A1, bl0, bl1);
                mma16(c[1][j], Q1, bq0, bq1);
            }
        }
        bg[0] += __shfl_xor_sync(0xffffffffu, bg[0], 1);
        bg[0] += __shfl_xor_sync(0xffffffffu, bg[0], 2);
        bg[1] += __shfl_xor_sync(0xffffffffu, bg[1], 1);
        bg[1] += __shfl_xor_sync(0xffffffffu, bg[1], 2);
        bg[2] += __shfl_xor_sync(0xffffffffu, bg[2], 1);
        bg[2] += __shfl_xor_sync(0xffffffffu, bg[2], 2);
        bg[3] += __shfl_xor_sync(0xffffffffu, bg[3], 1);
        bg[3] += __shfl_xor_sync(0xffffffffu, bg[3], 2);

        // ---- epilogue per m16 tile: lse + stage + coalesced copy-out ----
        #pragma unroll
        for (int u = 0; u < 2; u++) {
            #pragma unroll
            for (int h = 0; h < 2; h++) {
                float lpbg = -0.5f * (C0 + bg[2 * u + h]);
                float lp[16], y[16];
                float mx = -3.4e38f;
                #pragma unroll
                for (int j = 0; j < 8; j++) {
                    int col = 8 * j + 2 * t4;
                    float v0 = fmaf(-0.5f, c[u][j][2*h],   offs_s[col])   + lpbg;
                    float v1 = fmaf(-0.5f, c[u][j][2*h+1], offs_s[col+1]) + lpbg;
                    lp[2*j] = v0; lp[2*j+1] = v1;
                    y[2*j]   = v0 + lpi_s[col];
                    y[2*j+1] = v1 + lpi_s[col+1];
                    mx = fmaxf(mx, fmaxf(y[2*j], y[2*j+1]));
                }
                mx = fmaxf(mx, __shfl_xor_sync(0xffffffffu, mx, 1));
                mx = fmaxf(mx, __shfl_xor_sync(0xffffffffu, mx, 2));

                float mxl = mx * LOG2E_F;
                __half2 e0 = ex2_h2(fmaf(y[0],  LOG2E_F, -mxl), fmaf(y[1],  LOG2E_F, -mxl));
                __half2 e1 = ex2_h2(fmaf(y[2],  LOG2E_F, -mxl), fmaf(y[3],  LOG2E_F, -mxl));
                __half2 e2 = ex2_h2(fmaf(y[4],  LOG2E_F, -mxl), fmaf(y[5],  LOG2E_F, -mxl));
                __half2 e3 = ex2_h2(fmaf(y[6],  LOG2E_F, -mxl), fmaf(y[7],  LOG2E_F, -mxl));
                __half2 e4 = ex2_h2(fmaf(y[8],  LOG2E_F, -mxl), fmaf(y[9],  LOG2E_F, -mxl));
                __half2 e5 = ex2_h2(fmaf(y[10], LOG2E_F, -mxl), fmaf(y[11], LOG2E_F, -mxl));
                __half2 e6 = ex2_h2(fmaf(y[12], LOG2E_F, -mxl), fmaf(y[13], LOG2E_F, -mxl));
                __half2 e7 = ex2_h2(fmaf(y[14], LOG2E_F, -mxl), fmaf(y[15], LOG2E_F, -mxl));
                __half2 s01 = __hadd2(e0, e1), s23 = __hadd2(e2, e3);
                __half2 s45 = __hadd2(e4, e5), s67 = __hadd2(e6, e7);
                float2 f0 = __half22float2(s01), f1 = __half22float2(s23);
                float2 f2 = __half22float2(s45), f3 = __half22float2(s67);
                float se = (f0.x + f0.y) + (f1.x + f1.y)
                         + (f2.x + f2.y) + (f3.x + f3.y);
                se += __shfl_xor_sync(0xffffffffu, se, 1);
                se += __shfl_xor_sync(0xffffffffu, se, 2);
                if (t4 == 0) lsesum += (double)(mx + __logf(se));

                // stage this m16-tile row (stride-68 padded; STS.64 8B-aligned)
                float* srow = stg + (8 * h + g) * 68 + 2 * t4;
                #pragma unroll
                for (int j = 0; j < 8; j++)
                    *(float2*)(srow + 8 * j) = make_float2(lp[2*j], lp[2*j+1]);
            }
            __syncwarp();
            // coalesced copy-out of 16 rows (1024 floats); out+65 is 4B-aligned
            float* ob = out + 65 + (size_t)(row0 + 16 * u) * Kk;
            #pragma unroll
            for (int i = 0; i < 32; i++) {
                int idx = i * 32 + lane;
                ob[idx] = stg[(idx >> 6) * 68 + (idx & 63)];
            }
            __syncwarp();
        }
    }

    // ---- loss reduce + last-CTA finalize (deterministic replay reset) ----
    #pragma unroll
    for (int s = 16; s; s >>= 1)
        lsesum += __shfl_xor_sync(0xffffffffu, lsesum, s);
    if (lane == 0) wsum[wid] = lsesum;
    __syncthreads();
    if (tid == 0) {
        double bsum = 0.0;
        #pragma unroll
        for (int w = 0; w < TPB / 32; w++) bsum += wsum[w];
        atomicAdd(&g_lse, bsum);
        __threadfence();
        unsigned int old = atomicAdd(&g_count, 1u);
        if (old == GRID - 1) {
            __threadfence();
            double total = atomicAdd(&g_lse, 0.0);
            out[0] = (float)((double)kl_s * (double)Nn - total);
            g_lse   = 0.0;
            g_tile  = 0u;       // reset AFTER all warps exited their loops
            g_count = 0u;
        }
    }
}

// ---------------------------------------------------------------------------
extern "C" void kernel_launch(void* const* d_in, const int* in_sizes, int n_in,
                              void* d_out, int out_size)
{
    const float* X  = (const float*)d_in[0];
    const float* u  = (const float*)d_in[1];
    const float* pl = (const float*)d_in[2];
    const float* mu = (const float*)d_in[3];
    const float* lv = (const float*)d_in[4];
    const float* pi = (const float*)d_in[5];
    const float* pp = (const float*)d_in[6];
    float* out = (float*)d_out;

    cudaFuncSetAttribute(gmm_kernel,
                         cudaFuncAttributeMaxDynamicSharedMemorySize, SMEM_BYTES);

    gmm_kernel<<<GRID, TPB, SMEM_BYTES>>>(X, u, pl, mu, lv, pi, pp, out);
}